// round 10
// baseline (speedup 1.0000x reference)
#include <cuda_runtime.h>
#include <cstdint>

// CoordsToNRF: out[b, p] = atoms_flat[p] * (AU2KCALMOLA / MAX_NRF) / ||c_i - c_j||^2
// p = i*(i-1)/2 + j over the strict lower triangle of 128 atoms. B=2048, NC2=8128.
//
// Round-10 (R9 fix): MODE 2 no longer clamps the j_a atom index (always
// in-bounds); only the +32 read is clamped (it can touch index 8128 on the
// masked edge lane at i=127). Everything else as R9: 64-wide j tiles,
// 2 j's/thread, packed f32x2 batch pair -> 128 outputs per warp-row.

#define N_ATOMS 128
#define NC2     8128
#define BLOCK_THREADS 256              // 8 warps, one batch PAIR per block

typedef unsigned long long u64;

__device__ __forceinline__ u64 f2_add(u64 a, u64 b) {
    u64 r; asm("add.rn.f32x2 %0, %1, %2;" : "=l"(r) : "l"(a), "l"(b)); return r;
}
__device__ __forceinline__ u64 f2_mul(u64 a, u64 b) {
    u64 r; asm("mul.rn.f32x2 %0, %1, %2;" : "=l"(r) : "l"(a), "l"(b)); return r;
}
__device__ __forceinline__ u64 f2_fma(u64 a, u64 b, u64 c) {
    u64 r; asm("fma.rn.f32x2 %0, %1, %2, %3;" : "=l"(r) : "l"(a), "l"(b), "l"(c)); return r;
}
__device__ __forceinline__ float2 f2_lohi(u64 v) {
    float2 f; asm("mov.b64 {%0, %1}, %2;" : "=f"(f.x), "=f"(f.y) : "l"(v)); return f;
}

// Predicated store pair: batch0 at [o], batch1 at [o + NC2*4 = 32512]. @P STG only.
__device__ __forceinline__ void stg2_pred(float* o, float v0, float v1, int pred) {
    asm volatile("{\n\t"
        ".reg .pred p;\n\t"
        "setp.ne.b32 p, %0, 0;\n\t"
        "@p st.global.f32 [%1], %2;\n\t"
        "@p st.global.f32 [%1+32512], %3;\n\t"
        "}" :: "r"(pred), "l"(o), "f"(v0), "f"(v1) : "memory");
}

__device__ __forceinline__ float nrf_scale() {
    return (float)(627.5095 * 0.529177 / 100.0);
}

// MODE 0: all lanes valid (tile0, i>=64). MODE 1: partial tile0, vlim = i.
// MODE 2: partial tile1, vlim = i - 64, only the +32 atom read clamped.
template <int MODE>
__device__ __forceinline__ void do_rows(const float* __restrict__ sc,
                                        const float* __restrict__ atoms,
                                        float* __restrict__ ob,
                                        int j0, int i_first, int lane,
                                        float scale) {
    const int ja = j0 + lane;
    const int jb = ja + 32;
    const u64 S = 0x8000000080000000ull;   // packed f32x2 sign flip

    const ulonglong2 a_xy = *reinterpret_cast<const ulonglong2*>(&sc[ja * 8]);
    const u64        a_z  = *reinterpret_cast<const u64*>(&sc[ja * 8 + 4]);
    const ulonglong2 b_xy = *reinterpret_cast<const ulonglong2*>(&sc[jb * 8]);
    const u64        b_z  = *reinterpret_cast<const u64*>(&sc[jb * 8 + 4]);
    const u64 nax = a_xy.x ^ S, nay = a_xy.y ^ S, naz = a_z ^ S;
    const u64 nbx = b_xy.x ^ S, nby = b_xy.y ^ S, nbz = b_z ^ S;

    #pragma unroll 4
    for (int k = 0; k < 8; k++) {
        const int i = i_first + 8 * k;          // always <= 127 in every mode
        const int pbase = (i * (i - 1)) >> 1;

        const ulonglong2 cixy = *reinterpret_cast<const ulonglong2*>(&sc[i * 8]);
        const u64        ciz  = *reinterpret_cast<const u64*>(&sc[i * 8 + 4]);

        const u64 dxa = f2_add(cixy.x, nax);
        const u64 dya = f2_add(cixy.y, nay);
        const u64 dza = f2_add(ciz,    naz);
        const u64 d2a = f2_fma(dza, dza, f2_fma(dya, dya, f2_mul(dxa, dxa)));

        const u64 dxb = f2_add(cixy.x, nbx);
        const u64 dyb = f2_add(cixy.y, nby);
        const u64 dzb = f2_add(ciz,    nbz);
        const u64 d2b = f2_fma(dzb, dzb, f2_fma(dyb, dyb, f2_mul(dxb, dxb)));

        const int p = pbase + ja;               // in [0, NC2-1] in every mode
        // Only p+32 can reach NC2 (masked edge lane at i=127 in MODE 2).
        const int pb = (MODE == 2) ? ((p + 32 < NC2) ? (p + 32) : (NC2 - 1))
                                   : (p + 32);
        const float av_a = __ldg(&atoms[p])  * scale;
        const float av_b = __ldg(&atoms[pb]) * scale;

        const float2 da = f2_lohi(d2a);
        const float2 db = f2_lohi(d2b);
        const float r_a0 = __fdividef(av_a, da.x);   // j_a, batch 0
        const float r_a1 = __fdividef(av_a, da.y);   // j_a, batch 1
        const float r_b0 = __fdividef(av_b, db.x);
        const float r_b1 = __fdividef(av_b, db.y);

        float* o = ob + p;
        if (MODE == 0) {
            o[0]        = r_a0;
            o[32]       = r_b0;
            o[NC2]      = r_a1;
            o[NC2 + 32] = r_b1;
        } else {
            const int vlim = (MODE == 2) ? (i - 64) : i;
            stg2_pred(o,      r_a0, r_a1, lane      < vlim);
            stg2_pred(o + 32, r_b0, r_b1, lane + 32 < vlim);
        }
    }
}

__global__ __launch_bounds__(BLOCK_THREADS, 7)
void coords_to_nrf_kernel(const float* __restrict__ coords,
                          const float* __restrict__ atoms_flat,
                          float* __restrict__ out) {
    // Packed pair coords: atom a -> {x0,x1,y0,y1,z0,z1,pad,pad}: 4KB.
    __shared__ float sc[N_ATOMS * 8];

    const int warp = threadIdx.x >> 5;
    const int lane = threadIdx.x & 31;
    const int bg   = blockIdx.x;           // batch pair index

    const float* cb = coords + (size_t)bg * 2 * (N_ATOMS * 3);
    #pragma unroll
    for (int idx = threadIdx.x; idx < 2 * N_ATOMS * 3; idx += BLOCK_THREADS) {
        const int q   = idx / (N_ATOMS * 3);
        const int rem = idx - q * (N_ATOMS * 3);
        const int a   = rem / 3;
        const int d   = rem - a * 3;
        sc[a * 8 + d * 2 + q] = cb[idx];
    }
    __syncthreads();

    const float scale = nrf_scale();
    float* ob = out + (size_t)bg * 2 * NC2;

    // Region A: tile0 (j0=0), full rows i = 64..127 (i = 64+warp+8k).
    do_rows<0>(sc, atoms_flat, ob, 0, 64 + warp, lane, scale);
    // Region B: tile0, partial rows i = 0..63 (i=0 dead, predicated off).
    do_rows<1>(sc, atoms_flat, ob, 0, warp, lane, scale);
    // Region C: tile1 (j0=64), rows i = 64..127 (i=64 dead, predicated off).
    do_rows<2>(sc, atoms_flat, ob, 64, 64 + warp, lane, scale);
}

extern "C" void kernel_launch(void* const* d_in, const int* in_sizes, int n_in,
                              void* d_out, int out_size) {
    const float* coords     = (const float*)d_in[0];  // [2048, 128, 3] f32
    const float* atoms_flat = (const float*)d_in[1];  // [8128] f32
    float* out = (float*)d_out;                       // [2048, 8128] f32

    const int batch = in_sizes[0] / (N_ATOMS * 3);    // 2048
    coords_to_nrf_kernel<<<batch / 2, BLOCK_THREADS>>>(coords, atoms_flat, out);
}

// round 11
// speedup vs baseline: 1.3887x; 1.3887x over previous
#include <cuda_runtime.h>
#include <cstdint>

// CoordsToNRF: out[b, p] = atoms_flat[p] * (AU2KCALMOLA / MAX_NRF) / ||c_i - c_j||^2
// p = i*(i-1)/2 + j over the strict lower triangle of 128 atoms. B=2048, NC2=8128.
//
// Round-11: revert to the R7 structure (flat 316-row chunks, 8 warps x batch
// pair, branch-free body, C++ predicated stores) and remove the f32x2 pack
// MOVs by loading ci/cj directly from pair-packed smem as 64-bit lane pairs.

#define N_ATOMS 128
#define NC2     8128
#define BLOCK_THREADS 256      // 8 warps, one batch PAIR per block

typedef unsigned long long u64;

__device__ __forceinline__ u64 f2_add(u64 a, u64 b) {
    u64 r; asm("add.rn.f32x2 %0, %1, %2;" : "=l"(r) : "l"(a), "l"(b)); return r;
}
__device__ __forceinline__ u64 f2_mul(u64 a, u64 b) {
    u64 r; asm("mul.rn.f32x2 %0, %1, %2;" : "=l"(r) : "l"(a), "l"(b)); return r;
}
__device__ __forceinline__ u64 f2_fma(u64 a, u64 b, u64 c) {
    u64 r; asm("fma.rn.f32x2 %0, %1, %2, %3;" : "=l"(r) : "l"(a), "l"(b), "l"(c)); return r;
}
__device__ __forceinline__ float2 f2_lohi(u64 v) {
    float2 f; asm("mov.b64 {%0, %1}, %2;" : "=f"(f.x), "=f"(f.y) : "l"(v)); return f;
}

__device__ __forceinline__ float nrf_scale() {
    return (float)(627.5095 * 0.529177 / 100.0);
}

__global__ __launch_bounds__(BLOCK_THREADS, 7)
void coords_to_nrf_kernel(const float* __restrict__ coords,
                          const float* __restrict__ atoms_flat,
                          float* __restrict__ out) {
    // Packed pair coords: atom a -> {x0,x1,y0,y1,z0,z1,pad,pad}: 4KB.
    __shared__ float sc[N_ATOMS * 8];

    const int warp = threadIdx.x >> 5;    // 0..7 -> row chunk
    const int lane = threadIdx.x & 31;
    const int bg   = blockIdx.x;          // batch pair index

    // ---- Stage batch pair (gmem [b][atom][3] -> packed-pair smem) ----
    const float* cb = coords + (size_t)bg * 2 * (N_ATOMS * 3);
    #pragma unroll
    for (int idx = threadIdx.x; idx < 2 * N_ATOMS * 3; idx += BLOCK_THREADS) {
        const int q   = idx / (N_ATOMS * 3);       // batch in pair
        const int rem = idx - q * (N_ATOMS * 3);
        const int a   = rem / 3;
        const int d   = rem - a * 3;
        sc[a * 8 + d * 2 + q] = cb[idx];
    }
    __syncthreads();

    const float scale = nrf_scale();
    const u64 S = 0x8000000080000000ull;           // packed f32x2 sign flip

    // Flat rows [0,316) split: 40,40,40,40,39,39,39,39.
    const int over = (warp > 4) ? (warp - 4) : 0;
    const int r0 = 40 * warp - over;
    const int r1 = r0 + ((warp < 4) ? 40 : 39);

    const int starts[5] = {0, 127, 222, 285, 316};

    float* ob = out + (size_t)bg * 2 * NC2;        // batch q=0 plane

    #pragma unroll
    for (int seg = 0; seg < 4; seg++) {
        const int a = (r0 > starts[seg])     ? r0 : starts[seg];
        const int b = (r1 < starts[seg + 1]) ? r1 : starts[seg + 1];
        if (a >= b) continue;

        const int j0 = seg * 32;
        const int j  = j0 + lane;

        // cj pair straight from smem as 64-bit lane pairs, negated once.
        const ulonglong2 cj_xy = *reinterpret_cast<const ulonglong2*>(&sc[j * 8]);
        const u64        cj_z  = *reinterpret_cast<const u64*>(&sc[j * 8 + 4]);
        const u64 ncjx = cj_xy.x ^ S;
        const u64 ncjy = cj_xy.y ^ S;
        const u64 ncjz = cj_z   ^ S;

        const int i0 = j0 + 1 + (a - starts[seg]);
        int pbase = (i0 * (i0 - 1)) >> 1;
        const int iend = i0 + (b - a);

        #pragma unroll 4
        for (int i = i0; i < iend; i++) {
            // ci pair: LDS.128 + LDS.64, uniform address -> broadcast.
            const ulonglong2 cixy = *reinterpret_cast<const ulonglong2*>(&sc[i * 8]);
            const u64        ciz  = *reinterpret_cast<const u64*>(&sc[i * 8 + 4]);

            const u64 dx2 = f2_add(cixy.x, ncjx);
            const u64 dy2 = f2_add(cixy.y, ncjy);
            const u64 dz2 = f2_add(ciz,    ncjz);
            const u64 d2p = f2_fma(dz2, dz2, f2_fma(dy2, dy2, f2_mul(dx2, dx2)));

            const float2 d2 = f2_lohi(d2p);

            const int p  = pbase + j;
            const int pc = (p < NC2 - 1) ? p : (NC2 - 1);  // masked-lane safety
            const float aval = __ldg(&atoms_flat[pc]) * scale;
            const float ra = __fdividef(aval, d2.x);        // batch 0
            const float rb = __fdividef(aval, d2.y);        // batch 1

            if (j < i) {               // bare predicated store pair -> @P STG
                ob[p]       = ra;
                ob[p + NC2] = rb;
            }
            pbase += i;
        }
    }
}

extern "C" void kernel_launch(void* const* d_in, const int* in_sizes, int n_in,
                              void* d_out, int out_size) {
    const float* coords     = (const float*)d_in[0];  // [2048, 128, 3] f32
    const float* atoms_flat = (const float*)d_in[1];  // [8128] f32
    float* out = (float*)d_out;                       // [2048, 8128] f32

    const int batch = in_sizes[0] / (N_ATOMS * 3);    // 2048
    coords_to_nrf_kernel<<<batch / 2, BLOCK_THREADS>>>(coords, atoms_flat, out);
}